// round 4
// baseline (speedup 1.0000x reference)
#include <cuda_runtime.h>
#include <cstdint>

#define N_NODES 50000
#define N_EDGES 800000
#define D 64
#define CAP 64              // total bucket capacity per node
#define NSHARD 4            // counter shards per node
#define SHCAP 16            // slots per shard (NSHARD * SHCAP == CAP)

// -------- device scratch (no allocations allowed; zero-initialized) --------
__device__ float4 g_acc[N_NODES * (D / 4)];       // N_h * indeg
__device__ int    g_cnt[NSHARD][N_NODES];         // sharded cursors
__device__ uint2  g_edges[N_NODES * CAP];         // buckets: (src, w-bits)
__device__ uint4  g_ovf[4096];                    // overflow records (src,dst,w,-)
__device__ int    g_ovf_cnt;

// ---------------------------------------------------------------------------
// 1. scatter edges into sharded dst-buckets: rec = (src, w = ew*outdeg[src]).
//    4 edges/thread; shard rotates per edge to spread atomic contention.
//    Relies on g_cnt == 0 on entry (zero-init / reset by accum_kernel).
// ---------------------------------------------------------------------------
__global__ void scatter_kernel(const int* __restrict__ src,
                               const int* __restrict__ dst,
                               const float* __restrict__ ew,
                               const float* __restrict__ outdeg) {
    int t = blockIdx.x * blockDim.x + threadIdx.x;
    if (t >= N_EDGES / 4) return;

    int4   s4 = ((const int4*)src)[t];
    int4   d4 = ((const int4*)dst)[t];
    float4 w4 = ((const float4*)ew)[t];

    int   ss[4] = {s4.x, s4.y, s4.z, s4.w};
    int   dd[4] = {d4.x, d4.y, d4.z, d4.w};
    float ww[4] = {w4.x, w4.y, w4.z, w4.w};

#pragma unroll
    for (int i = 0; i < 4; i++) {
        float w = ww[i] * __ldg(&outdeg[ss[i]]);
        int sh = (t + i) & (NSHARD - 1);
        int pos = atomicAdd(&g_cnt[sh][dd[i]], 1);
        if (pos < SHCAP) {
            g_edges[dd[i] * CAP + sh * SHCAP + pos] =
                make_uint2((unsigned)ss[i], __float_as_uint(w));
        } else {
            int op = atomicAdd(&g_ovf_cnt, 1);
            if (op < 4096)
                g_ovf[op] = make_uint4((unsigned)ss[i], (unsigned)dd[i],
                                       __float_as_uint(w), 0u);
        }
    }
}

// ---------------------------------------------------------------------------
// 2. accumulate: 16 lanes per node. Per shard: preload all records into regs
//    (predicated uint4 loads), then issue all gathers back-to-back (MLP~16).
//    Fuses in_sqrt_degree scaling. Resets g_cnt for the next graph replay.
// ---------------------------------------------------------------------------
__global__ void accum_kernel(const float* __restrict__ embed,
                             const float* __restrict__ indeg) {
    int gid = blockIdx.x * blockDim.x + threadIdx.x;
    int n = gid >> 4;
    if (n >= N_NODES) return;
    int c = gid & 15;

    int cs[NSHARD];
    bool ovf = false;
#pragma unroll
    for (int s = 0; s < NSHARD; s++) {
        int v = g_cnt[s][n];
        ovf |= (v > SHCAP);
        cs[s] = v < SHCAP ? v : SHCAP;
    }
    __syncwarp();                       // all lanes done reading counters
    if (c < NSHARD) g_cnt[c][n] = 0;    // reset for next call

    float4 a0 = make_float4(0.f, 0.f, 0.f, 0.f);
    float4 a1 = make_float4(0.f, 0.f, 0.f, 0.f);

#pragma unroll
    for (int s = 0; s < NSHARD; s++) {
        int cnt = cs[s];
        if (cnt == 0) continue;
        const uint4* bp = (const uint4*)(g_edges + (size_t)n * CAP + s * SHCAP);

        uint4 r[SHCAP / 2];
#pragma unroll
        for (int k = 0; k < SHCAP / 2; k++)
            if (2 * k < cnt) r[k] = __ldg(&bp[k]);

#pragma unroll
        for (int j = 0; j < SHCAP; j++) {
            if (j < cnt) {
                unsigned sn = (j & 1) ? r[j >> 1].z : r[j >> 1].x;
                float w = __uint_as_float((j & 1) ? r[j >> 1].w : r[j >> 1].y);
                float4 v = __ldg((const float4*)(embed + (size_t)sn * D) + c);
                if (j & 2) {
                    a1.x = fmaf(v.x, w, a1.x); a1.y = fmaf(v.y, w, a1.y);
                    a1.z = fmaf(v.z, w, a1.z); a1.w = fmaf(v.w, w, a1.w);
                } else {
                    a0.x = fmaf(v.x, w, a0.x); a0.y = fmaf(v.y, w, a0.y);
                    a0.z = fmaf(v.z, w, a0.z); a0.w = fmaf(v.w, w, a0.w);
                }
            }
        }
    }

    // overflow fallback (effectively never taken; correctness guard)
    if (ovf) {
        int m = g_ovf_cnt;
        if (m > 4096) m = 4096;
        for (int i = 0; i < m; i++) {
            uint4 rec = g_ovf[i];
            if ((int)rec.y == n) {
                float w = __uint_as_float(rec.z);
                float4 v = __ldg((const float4*)(embed + (size_t)rec.x * D) + c);
                a0.x = fmaf(v.x, w, a0.x); a0.y = fmaf(v.y, w, a0.y);
                a0.z = fmaf(v.z, w, a0.z); a0.w = fmaf(v.w, w, a0.w);
            }
        }
    }

    float ind = __ldg(&indeg[n]);
    g_acc[n * (D / 4) + c] = make_float4((a0.x + a1.x) * ind,
                                         (a0.y + a1.y) * ind,
                                         (a0.z + a1.z) * ind,
                                         (a0.w + a1.w) * ind);
}

// ---------------------------------------------------------------------------
// 3. out = LeakyReLU((embed + acc) @ W^T + b)   [acc already * indeg]
//    4 rows/warp, packed fma.rn.f32x2. Also resets g_ovf_cnt for next call.
// ---------------------------------------------------------------------------
__device__ __forceinline__ unsigned long long pack_f2(float lo, float hi) {
    unsigned long long r;
    asm("mov.b64 %0, {%1, %2};" : "=l"(r) : "f"(lo), "f"(hi));
    return r;
}
__device__ __forceinline__ void unpack_f2(unsigned long long v, float& lo, float& hi) {
    asm("mov.b64 {%0, %1}, %2;" : "=f"(lo), "=f"(hi) : "l"(v));
}
__device__ __forceinline__ unsigned long long fma_f2(unsigned long long a,
                                                     unsigned long long b,
                                                     unsigned long long c) {
    unsigned long long d;
    asm("fma.rn.f32x2 %0, %1, %2, %3;" : "=l"(d) : "l"(a), "l"(b), "l"(c));
    return d;
}

#define ROWS_PER_WARP 4
#define N_QUADS (N_NODES / ROWS_PER_WARP)

__global__ void out_kernel(const float* __restrict__ embed,
                           const float* __restrict__ W,
                           const float* __restrict__ b,
                           float* __restrict__ out) {
    __shared__ float Wt[D * D];
    __shared__ float bs[D];

    if (blockIdx.x == 0 && threadIdx.x == 0) g_ovf_cnt = 0;  // reset for next call

    for (int i = threadIdx.x; i < D * D; i += blockDim.x) {
        int j = i >> 6;
        int k = i & 63;
        Wt[k * D + j] = W[i];
    }
    if (threadIdx.x < D) bs[threadIdx.x] = b[threadIdx.x];
    __syncthreads();

    int warp = threadIdx.x >> 5;
    int lane = threadIdx.x & 31;
    int wpb = blockDim.x >> 5;
    int nwarps = wpb * gridDim.x;

    const float* accf = (const float*)g_acc;

    for (int q = blockIdx.x * wpb + warp; q < N_QUADS; q += nwarps) {
        int r = q * ROWS_PER_WARP;

        float x0[ROWS_PER_WARP], x1[ROWS_PER_WARP];
#pragma unroll
        for (int rr = 0; rr < ROWS_PER_WARP; rr++) {
            const float* eb = embed + (size_t)(r + rr) * D;
            const float* ac = accf + (size_t)(r + rr) * D;
            x0[rr] = eb[lane]      + ac[lane];
            x1[rr] = eb[lane + 32] + ac[lane + 32];
        }

        unsigned long long bias = pack_f2(bs[2 * lane], bs[2 * lane + 1]);
        unsigned long long acc[ROWS_PER_WARP];
#pragma unroll
        for (int rr = 0; rr < ROWS_PER_WARP; rr++) acc[rr] = bias;

#pragma unroll
        for (int k = 0; k < D; k++) {
            float2 wv = *(const float2*)(Wt + k * D + 2 * lane);
            unsigned long long ww = pack_f2(wv.x, wv.y);
#pragma unroll
            for (int rr = 0; rr < ROWS_PER_WARP; rr++) {
                float xk = __shfl_sync(0xffffffffu,
                                       (k < 32) ? x0[rr] : x1[rr], k & 31);
                acc[rr] = fma_f2(pack_f2(xk, xk), ww, acc[rr]);
            }
        }

#pragma unroll
        for (int rr = 0; rr < ROWS_PER_WARP; rr++) {
            float oa, ob;
            unpack_f2(acc[rr], oa, ob);
            oa = oa > 0.f ? oa : 0.01f * oa;
            ob = ob > 0.f ? ob : 0.01f * ob;
            *(float2*)(out + (size_t)(r + rr) * D + 2 * lane) =
                make_float2(oa, ob);
        }
    }
}

// ---------------------------------------------------------------------------
// kernel_launch — 3 launches total
// ---------------------------------------------------------------------------
extern "C" void kernel_launch(void* const* d_in, const int* in_sizes, int n_in,
                              void* d_out, int out_size) {
    const float* embed  = (const float*)d_in[0];
    const int*   src    = (const int*)d_in[1];
    const int*   dst    = (const int*)d_in[2];
    const float* ew     = (const float*)d_in[3];
    const float* outdeg = (const float*)d_in[4];
    const float* indeg  = (const float*)d_in[5];
    const float* W      = (const float*)d_in[6];
    const float* b      = (const float*)d_in[7];
    float* out = (float*)d_out;

    {   // 1. scatter into sharded buckets (4 edges/thread)
        int threads = 256;
        int blocks = (N_EDGES / 4 + threads - 1) / threads;
        scatter_kernel<<<blocks, threads>>>(src, dst, ew, outdeg);
    }
    {   // 2. per-node register accumulation (+ indeg scaling, self-resetting)
        long long total = (long long)N_NODES * 16;
        int threads = 256;
        int blocks = (int)((total + threads - 1) / threads);
        accum_kernel<<<blocks, threads>>>(embed, indeg);
    }
    {   // 3. fused GEMM + LeakyReLU (+ ovf counter reset)
        int threads = 256;
        int blocks = 148 * 8;
        out_kernel<<<blocks, threads>>>(embed, W, b, out);
    }
}

// round 5
// speedup vs baseline: 2.5044x; 2.5044x over previous
#include <cuda_runtime.h>
#include <cuda_fp16.h>
#include <cstdint>

#define N_NODES 50000
#define N_EDGES 800000
#define D 64
#define CAP 64

// -------- device scratch (zero-initialized; no allocations allowed) --------
__device__ __half   g_node16[N_NODES * D];     // fp16 (embed * outdeg)   6.4 MB
__device__ float    g_acc[N_NODES * D];        // fp32 N_h * indeg       12.8 MB
__device__ int      g_cnt[N_NODES];            // bucket cursors
__device__ uint32_t g_edges[N_NODES * CAP];    // (src<<16)|fp16(ew)     12.8 MB
__device__ uint4    g_ovf[4096];               // overflow (src,dst,w32,-)
__device__ int      g_ovf_cnt;

// ---------------------------------------------------------------------------
// 1. fused prep + scatter. 800K threads:
//    - prep: thread t converts embed elems [4t,4t+4) * outdeg to fp16
//    - scatter: thread t buckets edge t as (src<<16 | fp16(ew))
//    Relies on g_cnt == 0 on entry (zero-init / reset by accum_kernel).
// ---------------------------------------------------------------------------
__global__ void prep_scatter_kernel(const float* __restrict__ embed,
                                    const int* __restrict__ src,
                                    const int* __restrict__ dst,
                                    const float* __restrict__ ew,
                                    const float* __restrict__ outdeg) {
    int t = blockIdx.x * blockDim.x + threadIdx.x;
    if (t >= N_EDGES) return;

    // ---- prep: 3.2M elements = 800K float4 ----
    {
        float4 v = __ldg((const float4*)embed + t);
        float od = __ldg(&outdeg[t >> 4]);          // row = (4t)/64
        __half2 h0 = __floats2half2_rn(v.x * od, v.y * od);
        __half2 h1 = __floats2half2_rn(v.z * od, v.w * od);
        uint2 pk;
        pk.x = *reinterpret_cast<uint32_t*>(&h0);
        pk.y = *reinterpret_cast<uint32_t*>(&h1);
        ((uint2*)g_node16)[t] = pk;
    }

    // ---- scatter edge t ----
    {
        int s = __ldg(&src[t]);
        int d = __ldg(&dst[t]);
        float w = __ldg(&ew[t]);
        uint32_t rec = ((uint32_t)s << 16) |
                       (uint32_t)__half_as_ushort(__float2half_rn(w));
        int pos = atomicAdd(&g_cnt[d], 1);
        if (pos < CAP) {
            g_edges[d * CAP + pos] = rec;
        } else {
            int op = atomicAdd(&g_ovf_cnt, 1);
            if (op < 4096)
                g_ovf[op] = make_uint4((unsigned)s, (unsigned)d,
                                       __float_as_uint(w), 0u);
        }
    }
}

// ---------------------------------------------------------------------------
// 2. accumulate: 8 lanes per node (lane c owns 8 halves = 16B chunk).
//    Records loaded once per batch (coalesced LDG.32), broadcast via shfl.
//    fp32 accumulation, * indeg, fp32 store. Self-resets g_cnt.
// ---------------------------------------------------------------------------
__global__ void accum_kernel(const float* __restrict__ indeg) {
    int gid = blockIdx.x * blockDim.x + threadIdx.x;
    int n = gid >> 3;
    if (n >= N_NODES) return;
    int c = gid & 7;
    unsigned gmask = 0xFFu << ((threadIdx.x & 31) & 24);  // this 8-lane group

    int cntr = g_cnt[n];
    int cnt = cntr < CAP ? cntr : CAP;
    const uint32_t* bucket = g_edges + (size_t)n * CAP;

    float2 a0 = make_float2(0.f, 0.f), a1 = a0, a2 = a0, a3 = a0;

    for (int b = 0; b * 8 < cnt; b++) {
        uint32_t rb = __ldg(&bucket[b * 8 + c]);   // safe: always < CAP
        int rem = cnt - b * 8;
#pragma unroll
        for (int i = 0; i < 8; i++) {
            if (i < rem) {
                uint32_t rec = __shfl_sync(gmask, rb, i, 8);
                float w = __half2float(__ushort_as_half(
                              (unsigned short)(rec & 0xFFFFu)));
                uint4 hv = __ldg((const uint4*)(g_node16 +
                              (size_t)(rec >> 16) * D) + c);
                float2 f0 = __half22float2(*(__half2*)&hv.x);
                float2 f1 = __half22float2(*(__half2*)&hv.y);
                float2 f2 = __half22float2(*(__half2*)&hv.z);
                float2 f3 = __half22float2(*(__half2*)&hv.w);
                a0.x = fmaf(f0.x, w, a0.x); a0.y = fmaf(f0.y, w, a0.y);
                a1.x = fmaf(f1.x, w, a1.x); a1.y = fmaf(f1.y, w, a1.y);
                a2.x = fmaf(f2.x, w, a2.x); a2.y = fmaf(f2.y, w, a2.y);
                a3.x = fmaf(f3.x, w, a3.x); a3.y = fmaf(f3.y, w, a3.y);
            }
        }
    }

    // overflow fallback (effectively never taken)
    if (cntr > CAP) {
        int m = g_ovf_cnt; if (m > 4096) m = 4096;
        for (int i = 0; i < m; i++) {
            uint4 rec = g_ovf[i];
            if ((int)rec.y == n) {
                float w = __uint_as_float(rec.z);
                uint4 hv = __ldg((const uint4*)(g_node16 +
                              (size_t)rec.x * D) + c);
                float2 f0 = __half22float2(*(__half2*)&hv.x);
                float2 f1 = __half22float2(*(__half2*)&hv.y);
                float2 f2 = __half22float2(*(__half2*)&hv.z);
                float2 f3 = __half22float2(*(__half2*)&hv.w);
                a0.x = fmaf(f0.x, w, a0.x); a0.y = fmaf(f0.y, w, a0.y);
                a1.x = fmaf(f1.x, w, a1.x); a1.y = fmaf(f1.y, w, a1.y);
                a2.x = fmaf(f2.x, w, a2.x); a2.y = fmaf(f2.y, w, a2.y);
                a3.x = fmaf(f3.x, w, a3.x); a3.y = fmaf(f3.y, w, a3.y);
            }
        }
    }

    float ind = __ldg(&indeg[n]);
    float* op = g_acc + (size_t)n * D + c * 8;
    ((float4*)op)[0] = make_float4(a0.x * ind, a0.y * ind, a1.x * ind, a1.y * ind);
    ((float4*)op)[1] = make_float4(a2.x * ind, a2.y * ind, a3.x * ind, a3.y * ind);

    if (c == 0) g_cnt[n] = 0;   // reset for next replay (read-before-write in warp)
}

// ---------------------------------------------------------------------------
// 3. out = LeakyReLU((embed + acc) @ W^T + b)   [acc already * indeg]
//    Tiled GEMM: block = 128 rows x 64 cols, 128 threads, 8x8 per thread,
//    packed fma.rn.f32x2, W pairs read as packed LDS.128.
// ---------------------------------------------------------------------------
typedef unsigned long long ull;
__device__ __forceinline__ ull fma_f2(ull a, ull b, ull c) {
    ull d;
    asm("fma.rn.f32x2 %0, %1, %2, %3;" : "=l"(d) : "l"(a), "l"(b), "l"(c));
    return d;
}
__device__ __forceinline__ ull pack_f2(float lo, float hi) {
    ull r;
    asm("mov.b64 %0, {%1, %2};" : "=l"(r) : "f"(lo), "f"(hi));
    return r;
}
__device__ __forceinline__ void unpack_f2(ull v, float& lo, float& hi) {
    asm("mov.b64 {%0, %1}, %2;" : "=f"(lo), "=f"(hi) : "l"(v));
}

#define OB_ROWS 128

__global__ void __launch_bounds__(128) out_kernel(const float* __restrict__ embed,
                                                  const float* __restrict__ W,
                                                  const float* __restrict__ b,
                                                  float* __restrict__ out) {
    __shared__ float xs[OB_ROWS][D + 1];   // padded: conflict-free column reads
    __shared__ float Wt[D][D];             // Wt[k][j] = W[j][k]
    __shared__ float bs[D];

    int tid = threadIdx.x;
    if (blockIdx.x == 0 && tid == 0) g_ovf_cnt = 0;   // reset for next replay

    for (int i = tid; i < D * D; i += 128) {
        int j = i >> 6, k = i & 63;
        Wt[k][j] = W[i];
    }
    if (tid < D) bs[tid] = b[tid];

    int row0 = blockIdx.x * OB_ROWS;
    for (int i = tid; i < OB_ROWS * (D / 4); i += 128) {
        int r = i >> 4, q = i & 15;
        int gr = row0 + r;
        int grc = gr < N_NODES ? gr : N_NODES - 1;
        float4 e = __ldg((const float4*)(embed + (size_t)grc * D) + q);
        float4 a = *((const float4*)(g_acc + (size_t)grc * D) + q);
        xs[r][q * 4 + 0] = e.x + a.x;
        xs[r][q * 4 + 1] = e.y + a.y;
        xs[r][q * 4 + 2] = e.z + a.z;
        xs[r][q * 4 + 3] = e.w + a.w;
    }
    __syncthreads();

    int tx = tid & 7;        // col octet: cols [8tx, 8tx+8)
    int ty = tid >> 3;       // row octet: rows [8ty, 8ty+8)

    ull acc[8][4];
    {
        ulonglong2 b01 = *(const ulonglong2*)&bs[tx * 8];
        ulonglong2 b23 = *(const ulonglong2*)&bs[tx * 8 + 4];
#pragma unroll
        for (int rr = 0; rr < 8; rr++) {
            acc[rr][0] = b01.x; acc[rr][1] = b01.y;
            acc[rr][2] = b23.x; acc[rr][3] = b23.y;
        }
    }

#pragma unroll 4
    for (int k = 0; k < D; k++) {
        ulonglong2 w01 = *(const ulonglong2*)&Wt[k][tx * 8];
        ulonglong2 w23 = *(const ulonglong2*)&Wt[k][tx * 8 + 4];
#pragma unroll
        for (int rr = 0; rr < 8; rr++) {
            float xv = xs[ty * 8 + rr][k];
            ull xp = pack_f2(xv, xv);
            acc[rr][0] = fma_f2(xp, w01.x, acc[rr][0]);
            acc[rr][1] = fma_f2(xp, w01.y, acc[rr][1]);
            acc[rr][2] = fma_f2(xp, w23.x, acc[rr][2]);
            acc[rr][3] = fma_f2(xp, w23.y, acc[rr][3]);
        }
    }

#pragma unroll
    for (int rr = 0; rr < 8; rr++) {
        int gr = row0 + ty * 8 + rr;
        if (gr < N_NODES) {
            float o[8];
#pragma unroll
            for (int p = 0; p < 4; p++) unpack_f2(acc[rr][p], o[2 * p], o[2 * p + 1]);
#pragma unroll
            for (int q = 0; q < 8; q++) o[q] = o[q] > 0.f ? o[q] : 0.01f * o[q];
            float* dst = out + (size_t)gr * D + tx * 8;
            ((float4*)dst)[0] = make_float4(o[0], o[1], o[2], o[3]);
            ((float4*)dst)[1] = make_float4(o[4], o[5], o[6], o[7]);
        }
    }
}

// ---------------------------------------------------------------------------
// kernel_launch — 3 launches
// ---------------------------------------------------------------------------
extern "C" void kernel_launch(void* const* d_in, const int* in_sizes, int n_in,
                              void* d_out, int out_size) {
    const float* embed  = (const float*)d_in[0];
    const int*   src    = (const int*)d_in[1];
    const int*   dst    = (const int*)d_in[2];
    const float* ew     = (const float*)d_in[3];
    const float* outdeg = (const float*)d_in[4];
    const float* indeg  = (const float*)d_in[5];
    const float* W      = (const float*)d_in[6];
    const float* b      = (const float*)d_in[7];
    float* out = (float*)d_out;

    {   // 1. fused fp16 prep + bucket scatter
        int threads = 256;
        int blocks = N_EDGES / threads;            // 3125, exact
        prep_scatter_kernel<<<blocks, threads>>>(embed, src, dst, ew, outdeg);
    }
    {   // 2. gather-accumulate (8 lanes/node)
        int total = N_NODES * 8;
        int threads = 256;
        int blocks = (total + threads - 1) / threads;
        accum_kernel<<<blocks, threads>>>(indeg);
    }
    {   // 3. tiled GEMM + LeakyReLU
        int blocks = (N_NODES + OB_ROWS - 1) / OB_ROWS;   // 391
        out_kernel<<<blocks, 128>>>(embed, W, b, out);
    }
}